// round 3
// baseline (speedup 1.0000x reference)
#include <cuda_runtime.h>

// Laplacian_22711787061657
// x: (32, 1, 1024, 1024) fp32. Circular 2nd difference along H and W:
//   gx[h][w] = x[h-2][w] - 2*x[h-1][w] + x[h][w]   (mod 1024)
//   gy[h][w] = x[h][w-2] - 2*x[h][w-1] + x[h][w]   (mod 1024)
//   out = clip(gx+gy, -1, 1) * 0.5, NaN(x)->1.0 on input, NaN->0 on output.
//
// v3 = v1 structure (rolling H registers, CHUNK=64) +
//   - streaming stores (__stcs): output is write-once, keep it out of L2 so
//     the input stream + chunk-boundary preloads stay resident
//   - W-neighbor fetched as an aligned 8-byte float2 (tail of float4 w-4)
//     for all lanes uniformly: half the duplicate-read traffic, no shfl, no
//     divergence, fewer scrub ops.

#define HW 1024           // H == W == 1024
#define ROW_F4 (HW / 4)   // 256 float4 per row
#define CHUNK 64          // rows per block
#define NCHUNK (HW / CHUNK)

__device__ __forceinline__ float4 scrub1(float4 v) {
    v.x = isnan(v.x) ? 1.0f : v.x;
    v.y = isnan(v.y) ? 1.0f : v.y;
    v.z = isnan(v.z) ? 1.0f : v.z;
    v.w = isnan(v.w) ? 1.0f : v.w;
    return v;
}

__device__ __forceinline__ float finish(float gx, float gy) {
    // 0.5 * clip(gx+gy, -1, 1) == clamp(0.5*(gx+gy), -0.5, 0.5)
    float g = 0.5f * (gx + gy);
    g = fminf(0.5f, fmaxf(-0.5f, g));
    return isnan(g) ? 0.0f : g;   // remove_nan on output
}

__global__ __launch_bounds__(ROW_F4, 4)
void laplacian_kernel(const float4* __restrict__ x, float4* __restrict__ out) {
    const int t     = threadIdx.x;        // column float4 index, 0..255
    const int chunk = blockIdx.x;         // 0..NCHUNK-1
    const int b     = blockIdx.y;         // image index

    const size_t img_off = (size_t)b * (HW * ROW_F4);
    const float4* __restrict__ xi = x + img_off;
    float4* __restrict__ oi = out + img_off;

    const int tp = (t + ROW_F4 - 1) & (ROW_F4 - 1); // float4 at w-4 (circular)

    const int h0  = chunk * CHUNK;
    const int hm2 = (h0 + HW - 2) & (HW - 1);
    const int hm1 = (h0 + HW - 1) & (HW - 1);

    float4 rm2 = scrub1(xi[(size_t)hm2 * ROW_F4 + t]); // row h-2
    float4 rm1 = scrub1(xi[(size_t)hm1 * ROW_F4 + t]); // row h-1

    const float4* __restrict__ rin  = xi + (size_t)h0 * ROW_F4;
    float4*       __restrict__ rout = oi + (size_t)h0 * ROW_F4;

    #pragma unroll 4
    for (int i = 0; i < CHUNK; ++i) {
        const float4 a = scrub1(rin[t]);                       // elems 4t..4t+3
        // elems 4t-2, 4t-1: aligned 8B tail of float4 (t-1 mod 256).
        // Same cache line as a neighbor thread's 'a' load -> L1 hit.
        const float2 e = __ldg((const float2*)(rin + tp) + 1);
        const float pz = isnan(e.x) ? 1.0f : e.x;
        const float pw = isnan(e.y) ? 1.0f : e.y;

        float4 g;
        g.x = finish(rm2.x - 2.0f * rm1.x + a.x,  pz  - 2.0f * pw  + a.x);
        g.y = finish(rm2.y - 2.0f * rm1.y + a.y,  pw  - 2.0f * a.x + a.y);
        g.z = finish(rm2.z - 2.0f * rm1.z + a.z,  a.x - 2.0f * a.y + a.z);
        g.w = finish(rm2.w - 2.0f * rm1.w + a.w,  a.y - 2.0f * a.z + a.w);

        __stcs(rout + t, g);   // streaming store: evict-first, spare L2

        rm2 = rm1;
        rm1 = a;
        rin  += ROW_F4;
        rout += ROW_F4;
    }
}

extern "C" void kernel_launch(void* const* d_in, const int* in_sizes, int n_in,
                              void* d_out, int out_size) {
    const float4* x = (const float4*)d_in[0];
    float4* out = (float4*)d_out;
    const int batch = in_sizes[0] / (HW * HW); // 32

    dim3 grid(NCHUNK, batch);
    dim3 block(ROW_F4);
    laplacian_kernel<<<grid, block>>>(x, out);
}

// round 4
// speedup vs baseline: 1.2159x; 1.2159x over previous
#include <cuda_runtime.h>

// Laplacian_22711787061657
// x: (32, 1, 1024, 1024) fp32. Circular 2nd difference along H and W:
//   gx[h][w] = x[h-2][w] - 2*x[h-1][w] + x[h][w]   (mod 1024)
//   gy[h][w] = x[h][w-2] - 2*x[h][w-1] + x[h][w]   (mod 1024)
//   out = clip(gx+gy, -1, 1) * 0.5, NaN(x)->1.0 on input, NaN->0 on output.
//
// v4 = v1 inner loop EXACTLY (two float4 loads + plain float4 store; the
// duplicate row load is an L1 hit and proven fastest), with CHUNK=32:
//   grid 1024 blocks -> 1024 = 148*6 + 136, wave imbalance ~1.2% instead of
//   the 13.5% tail of grid=512 (68 SMs ran 4 CTAs while 80 ran 3).

#define HW 1024           // H == W == 1024
#define ROW_F4 (HW / 4)   // 256 float4 per row
#define CHUNK 32          // rows per block
#define NCHUNK (HW / CHUNK)

__device__ __forceinline__ float4 scrub1(float4 v) {
    // remove_nan(x, 1.0)
    v.x = isnan(v.x) ? 1.0f : v.x;
    v.y = isnan(v.y) ? 1.0f : v.y;
    v.z = isnan(v.z) ? 1.0f : v.z;
    v.w = isnan(v.w) ? 1.0f : v.w;
    return v;
}

__device__ __forceinline__ float finish(float gx, float gy) {
    // 0.5 * clip(gx+gy, -1, 1) == clamp(0.5*(gx+gy), -0.5, 0.5)
    float g = 0.5f * (gx + gy);
    g = fminf(0.5f, fmaxf(-0.5f, g));
    return isnan(g) ? 0.0f : g;   // remove_nan on output
}

__global__ __launch_bounds__(ROW_F4, 4)
void laplacian_kernel(const float4* __restrict__ x, float4* __restrict__ out) {
    const int t     = threadIdx.x;        // column float4 index, 0..255
    const int chunk = blockIdx.x;         // 0..NCHUNK-1
    const int b     = blockIdx.y;         // image index

    const size_t img_off = (size_t)b * (HW * ROW_F4);
    const float4* __restrict__ xi = x + img_off;
    float4* __restrict__ oi = out + img_off;

    const int tp = (t + ROW_F4 - 1) & (ROW_F4 - 1); // float4 at w-4 (circular)

    const int h0  = chunk * CHUNK;
    const int hm2 = (h0 + HW - 2) & (HW - 1);
    const int hm1 = (h0 + HW - 1) & (HW - 1);

    float4 rm2 = scrub1(xi[(size_t)hm2 * ROW_F4 + t]); // row h-2
    float4 rm1 = scrub1(xi[(size_t)hm1 * ROW_F4 + t]); // row h-1

    const float4* __restrict__ rin  = xi + (size_t)h0 * ROW_F4;
    float4*       __restrict__ rout = oi + (size_t)h0 * ROW_F4;

    #pragma unroll 4
    for (int i = 0; i < CHUNK; ++i) {
        const float4 a = scrub1(rin[t]);    // row h, elems 4t..4t+3
        const float4 p = scrub1(rin[tp]);   // row h, elems 4t-4..4t-1 (L1 hit)

        float4 g;
        g.x = finish(rm2.x - 2.0f * rm1.x + a.x,  p.z - 2.0f * p.w + a.x);
        g.y = finish(rm2.y - 2.0f * rm1.y + a.y,  p.w - 2.0f * a.x + a.y);
        g.z = finish(rm2.z - 2.0f * rm1.z + a.z,  a.x - 2.0f * a.y + a.z);
        g.w = finish(rm2.w - 2.0f * rm1.w + a.w,  a.y - 2.0f * a.z + a.w);

        rout[t] = g;

        rm2 = rm1;
        rm1 = a;
        rin  += ROW_F4;
        rout += ROW_F4;
    }
}

extern "C" void kernel_launch(void* const* d_in, const int* in_sizes, int n_in,
                              void* d_out, int out_size) {
    const float4* x = (const float4*)d_in[0];
    float4* out = (float4*)d_out;
    const int batch = in_sizes[0] / (HW * HW); // 32

    dim3 grid(NCHUNK, batch);
    dim3 block(ROW_F4);
    laplacian_kernel<<<grid, block>>>(x, out);
}